// round 1
// baseline (speedup 1.0000x reference)
#include <cuda_runtime.h>
#include <float.h>

#define D 64
#define K 512
#define BLOCK 512

// scratch accumulator for the loss (allocation-free: __device__ global)
__device__ double g_acc;

__global__ void vq_zero_acc() { g_acc = 0.0; }

// One thread per row. Embeddings (transposed to [k][d]) + per-code norms in
// dynamic shared memory. Warp lanes = consecutive rows, so all e-loads are
// uniform-address broadcasts (no bank conflicts, LDS never binds).
__global__ void __launch_bounds__(BLOCK)
vq_kernel(const float* __restrict__ x, const float* __restrict__ emb,
          float* __restrict__ out, int nrows)
{
    extern __shared__ float smem[];
    float*  se    = smem;                 // K*D floats, layout [k][d]
    float*  snorm = smem + K * D;         // K floats
    double* sred  = (double*)(smem + K * D + K);  // BLOCK doubles

    const int tid = threadIdx.x;

    // Load embeddings (global layout: emb[d*K + k]) transposed into shared.
    for (int i = tid; i < K * D; i += BLOCK) {
        int d = i >> 9;        // i / 512
        int k = i & (K - 1);   // i % 512
        se[k * D + d] = emb[i];
    }
    __syncthreads();

    // Per-code squared norms.
    for (int k = tid; k < K; k += BLOCK) {
        const float* ek = se + k * D;
        float s = 0.f;
        #pragma unroll
        for (int d = 0; d < D; d++) s = fmaf(ek[d], ek[d], s);
        snorm[k] = s;
    }
    __syncthreads();

    const int row = blockIdx.x * BLOCK + tid;
    double mysum = 0.0;

    if (row < nrows) {
        // Load this row of x into registers (16 x float4).
        float4 xr[16];
        const float4* xp = (const float4*)(x + (size_t)row * D);
        float xnorm = 0.f;
        #pragma unroll
        for (int i = 0; i < 16; i++) {
            xr[i] = xp[i];
            xnorm = fmaf(xr[i].x, xr[i].x, xnorm);
            xnorm = fmaf(xr[i].y, xr[i].y, xnorm);
            xnorm = fmaf(xr[i].z, xr[i].z, xnorm);
            xnorm = fmaf(xr[i].w, xr[i].w, xnorm);
        }

        // Argmin over codes of (||e||^2 - 2 x.e) — equivalent to argmin distance.
        float best = FLT_MAX;
        int   bk   = 0;
        for (int k = 0; k < K; k++) {
            const float4* ek = (const float4*)(se + k * D);
            float a0 = 0.f, a1 = 0.f, a2 = 0.f, a3 = 0.f;
            #pragma unroll
            for (int i = 0; i < 16; i++) {
                float4 e = ek[i];   // broadcast LDS.128 (uniform across warp)
                a0 = fmaf(e.x, xr[i].x, a0);
                a1 = fmaf(e.y, xr[i].y, a1);
                a2 = fmaf(e.z, xr[i].z, a2);
                a3 = fmaf(e.w, xr[i].w, a3);
            }
            float dot  = (a0 + a1) + (a2 + a3);
            float dist = fmaf(-2.f, dot, snorm[k]);
            if (dist < best) { best = dist; bk = k; }
        }

        // True squared distance for the loss: ||x||^2 + (||e||^2 - 2 x.e)
        mysum = (double)(xnorm + best);

        // Quantized output = selected codebook row.
        float4* op = (float4*)(out + (size_t)row * D);
        const float4* eb = (const float4*)(se + bk * D);
        #pragma unroll
        for (int i = 0; i < 16; i++) op[i] = eb[i];
    }

    // Block reduction of squared distances (doubles), then one atomic per block.
    sred[tid] = mysum;
    __syncthreads();
    #pragma unroll
    for (int s = BLOCK / 2; s > 0; s >>= 1) {
        if (tid < s) sred[tid] += sred[tid + s];
        __syncthreads();
    }
    if (tid == 0) atomicAdd(&g_acc, sred[0]);
}

// loss = (1 + BETA) * sum_sq / (nrows * D), BETA = 0.25
__global__ void vq_finalize(float* __restrict__ out, int idx, double scale)
{
    out[idx] = (float)(g_acc * scale);
}

extern "C" void kernel_launch(void* const* d_in, const int* in_sizes, int n_in,
                              void* d_out, int out_size)
{
    const float* x   = (const float*)d_in[0];   // (64,32,32,64) = 4194304 floats
    const float* emb = (const float*)d_in[1];   // (64,512)      = 32768 floats
    float* out = (float*)d_out;

    const int nrows = in_sizes[0] / D;          // 65536
    const int grid  = (nrows + BLOCK - 1) / BLOCK;

    const int smem_bytes = (K * D + K) * (int)sizeof(float) + BLOCK * (int)sizeof(double);
    cudaFuncSetAttribute(vq_kernel, cudaFuncAttributeMaxDynamicSharedMemorySize, smem_bytes);

    vq_zero_acc<<<1, 1>>>();
    vq_kernel<<<grid, BLOCK, smem_bytes>>>(x, emb, out, nrows);

    if (out_size > nrows * D) {
        double scale = 1.25 / ((double)nrows * (double)D);
        vq_finalize<<<1, 1>>>(out, nrows * D, scale);
    }
}

// round 2
// speedup vs baseline: 1.4162x; 1.4162x over previous
#include <cuda_runtime.h>
#include <float.h>

#define D 64
#define K 512
#define BLOCK 224          // 7 warps
#define ROWS_PER_THREAD 2

// scratch accumulator for the loss (allocation-free: __device__ global)
__device__ double g_acc;

__global__ void vq_zero_acc() { g_acc = 0.0; }

// Packed fp32x2 FMA (Blackwell FFMA2): d = a*b + c, two fp32 lanes per op.
__device__ __forceinline__ unsigned long long ffma2(unsigned long long a,
                                                    unsigned long long b,
                                                    unsigned long long c) {
    unsigned long long d;
    asm volatile("fma.rn.f32x2 %0, %1, %2, %3;" : "=l"(d) : "l"(a), "l"(b), "l"(c));
    return d;
}
__device__ __forceinline__ unsigned long long fadd2(unsigned long long a,
                                                    unsigned long long b) {
    unsigned long long d;
    asm volatile("add.rn.f32x2 %0, %1, %2;" : "=l"(d) : "l"(a), "l"(b));
    return d;
}
__device__ __forceinline__ float2 unpack2(unsigned long long v) {
    float2 r;
    asm("mov.b64 {%0, %1}, %2;" : "=f"(r.x), "=f"(r.y) : "l"(v));
    return r;
}

// grid = 148 CTAs (one wave, all SMs). Each CTA owns a contiguous chunk of
// rows; each thread handles 2 rows (stride BLOCK) so every broadcast LDS of
// the codebook is amortized over 2 rows. Codebook transposed to [k][d] in
// shared; warp lanes process different rows in lockstep over codes, so all
// e-loads are uniform-address broadcasts (conflict-free).
__global__ void __launch_bounds__(BLOCK, 1)
vq_kernel(const float* __restrict__ x, const float* __restrict__ emb,
          float* __restrict__ out, int nrows, int rows_per_cta)
{
    extern __shared__ float smem[];
    float*  se    = smem;                          // K*D floats, [k][d]
    float*  snorm = smem + K * D;                  // K floats
    double* sred  = (double*)(smem + K * D + K);   // BLOCK doubles

    const int tid = threadIdx.x;

    // Load embeddings (global layout emb[d*K + k]) transposed into shared.
    for (int i = tid; i < K * D; i += BLOCK) {
        int d = i >> 9;        // i / 512
        int k = i & (K - 1);   // i % 512
        se[k * D + d] = emb[i];
    }
    __syncthreads();

    // Per-code squared norms.
    for (int k = tid; k < K; k += BLOCK) {
        const float* ek = se + k * D;
        float s = 0.f;
        #pragma unroll
        for (int d = 0; d < D; d++) s = fmaf(ek[d], ek[d], s);
        snorm[k] = s;
    }
    __syncthreads();

    const int base  = blockIdx.x * rows_per_cta;
    const int count = min(rows_per_cta, nrows - base);

    const int  row0 = base + tid;
    const int  row1 = base + tid + BLOCK;
    const bool v0   = (tid < count);
    const bool v1   = (tid + BLOCK < count);

    // x rows in registers as packed f32x2 (32 packs = 64 floats per row).
    unsigned long long xr0[32], xr1[32];
    float xn0 = 0.f, xn1 = 0.f;
    {
        const ulonglong2* p0 = (const ulonglong2*)(x + (size_t)row0 * D);
        const ulonglong2* p1 = (const ulonglong2*)(x + (size_t)row1 * D);
        #pragma unroll
        for (int j = 0; j < 16; j++) {
            ulonglong2 a = v0 ? p0[j] : make_ulonglong2(0ull, 0ull);
            ulonglong2 b = v1 ? p1[j] : make_ulonglong2(0ull, 0ull);
            xr0[2 * j] = a.x; xr0[2 * j + 1] = a.y;
            xr1[2 * j] = b.x; xr1[2 * j + 1] = b.y;
        }
        #pragma unroll
        for (int p = 0; p < 32; p++) {
            float2 a = unpack2(xr0[p]);
            float2 b = unpack2(xr1[p]);
            xn0 = fmaf(a.x, a.x, fmaf(a.y, a.y, xn0));
            xn1 = fmaf(b.x, b.x, fmaf(b.y, b.y, xn1));
        }
    }

    float best0 = FLT_MAX, best1 = FLT_MAX;
    int   bk0 = 0, bk1 = 0;

    for (int k = 0; k < K; k++) {
        const ulonglong2* ek = (const ulonglong2*)(se + k * D);
        unsigned long long a0 = 0, a1 = 0, a2 = 0, a3 = 0;   // row0 accums
        unsigned long long b0 = 0, b1 = 0, b2 = 0, b3 = 0;   // row1 accums
        #pragma unroll
        for (int j = 0; j < 16; j++) {
            ulonglong2 e = ek[j];    // broadcast LDS.128, shared by both rows
            if (j & 1) {
                a2 = ffma2(e.x, xr0[2 * j],     a2);
                a3 = ffma2(e.y, xr0[2 * j + 1], a3);
                b2 = ffma2(e.x, xr1[2 * j],     b2);
                b3 = ffma2(e.y, xr1[2 * j + 1], b3);
            } else {
                a0 = ffma2(e.x, xr0[2 * j],     a0);
                a1 = ffma2(e.y, xr0[2 * j + 1], a1);
                b0 = ffma2(e.x, xr1[2 * j],     b0);
                b1 = ffma2(e.y, xr1[2 * j + 1], b1);
            }
        }
        a0 = fadd2(fadd2(a0, a1), fadd2(a2, a3));
        b0 = fadd2(fadd2(b0, b1), fadd2(b2, b3));
        float2 sa = unpack2(a0);
        float2 sb = unpack2(b0);
        float dot0 = sa.x + sa.y;
        float dot1 = sb.x + sb.y;
        float nk = snorm[k];
        float d0 = fmaf(-2.f, dot0, nk);
        float d1 = fmaf(-2.f, dot1, nk);
        if (d0 < best0) { best0 = d0; bk0 = k; }
        if (d1 < best1) { best1 = d1; bk1 = k; }
    }

    double mysum = 0.0;
    if (v0) {
        mysum += (double)(xn0 + best0);
        float4* op = (float4*)(out + (size_t)row0 * D);
        const float4* eb = (const float4*)(se + bk0 * D);
        #pragma unroll
        for (int i = 0; i < 16; i++) op[i] = eb[i];
    }
    if (v1) {
        mysum += (double)(xn1 + best1);
        float4* op = (float4*)(out + (size_t)row1 * D);
        const float4* eb = (const float4*)(se + bk1 * D);
        #pragma unroll
        for (int i = 0; i < 16; i++) op[i] = eb[i];
    }

    // Block reduction (doubles), then one atomic per CTA.
    sred[tid] = mysum;
    __syncthreads();
    for (int s = 128; s > 0; s >>= 1) {
        if (tid < s && tid + s < BLOCK) sred[tid] += sred[tid + s];
        __syncthreads();
    }
    if (tid == 0) atomicAdd(&g_acc, sred[0]);
}

// loss = (1 + BETA) * sum_sq / (nrows * D), BETA = 0.25
__global__ void vq_finalize(float* __restrict__ out, int idx, double scale)
{
    out[idx] = (float)(g_acc * scale);
}

extern "C" void kernel_launch(void* const* d_in, const int* in_sizes, int n_in,
                              void* d_out, int out_size)
{
    const float* x   = (const float*)d_in[0];   // (64,32,32,64) = 4194304 floats
    const float* emb = (const float*)d_in[1];   // (64,512)      = 32768 floats
    float* out = (float*)d_out;

    const int nrows = in_sizes[0] / D;                    // 65536
    const int grid  = 148;                                // one wave on GB300
    const int rows_per_cta = (nrows + grid - 1) / grid;   // 443

    const int smem_bytes = (K * D + K) * (int)sizeof(float) + BLOCK * (int)sizeof(double);
    cudaFuncSetAttribute(vq_kernel, cudaFuncAttributeMaxDynamicSharedMemorySize, smem_bytes);

    vq_zero_acc<<<1, 1>>>();
    vq_kernel<<<grid, BLOCK, smem_bytes>>>(x, emb, out, nrows, rows_per_cta);

    if (out_size > nrows * D) {
        double scale = 1.25 / ((double)nrows * (double)D);
        vq_finalize<<<1, 1>>>(out, nrows * D, scale);
    }
}

// round 3
// speedup vs baseline: 1.4178x; 1.0011x over previous
#include <cuda_runtime.h>
#include <float.h>

#define D 64
#define K 512
#define BLOCK 224          // 7 warps
#define ROWS_PER_THREAD 2

// scratch accumulator for the loss (allocation-free: __device__ global)
__device__ double g_acc;

__global__ void vq_zero_acc() { g_acc = 0.0; }

// Packed fp32x2 FMA (Blackwell FFMA2): d = a*b + c, two fp32 lanes per op.
__device__ __forceinline__ unsigned long long ffma2(unsigned long long a,
                                                    unsigned long long b,
                                                    unsigned long long c) {
    unsigned long long d;
    asm volatile("fma.rn.f32x2 %0, %1, %2, %3;" : "=l"(d) : "l"(a), "l"(b), "l"(c));
    return d;
}
__device__ __forceinline__ unsigned long long fadd2(unsigned long long a,
                                                    unsigned long long b) {
    unsigned long long d;
    asm volatile("add.rn.f32x2 %0, %1, %2;" : "=l"(d) : "l"(a), "l"(b));
    return d;
}
__device__ __forceinline__ float2 unpack2(unsigned long long v) {
    float2 r;
    asm("mov.b64 {%0, %1}, %2;" : "=f"(r.x), "=f"(r.y) : "l"(v));
    return r;
}

// grid = 148 CTAs (one wave, all SMs). Each CTA owns a contiguous chunk of
// rows; each thread handles 2 rows (stride BLOCK) so every broadcast LDS of
// the codebook is amortized over 2 rows. Codebook transposed to [k][d] in
// shared; warp lanes process different rows in lockstep over codes, so all
// e-loads are uniform-address broadcasts (conflict-free).
__global__ void __launch_bounds__(BLOCK, 1)
vq_kernel(const float* __restrict__ x, const float* __restrict__ emb,
          float* __restrict__ out, int nrows, int rows_per_cta)
{
    extern __shared__ float smem[];
    float*  se    = smem;                          // K*D floats, [k][d]
    float*  snorm = smem + K * D;                  // K floats
    double* sred  = (double*)(smem + K * D + K);   // BLOCK doubles

    const int tid = threadIdx.x;

    // Load embeddings (global layout emb[d*K + k]) transposed into shared.
    for (int i = tid; i < K * D; i += BLOCK) {
        int d = i >> 9;        // i / 512
        int k = i & (K - 1);   // i % 512
        se[k * D + d] = emb[i];
    }
    __syncthreads();

    // Per-code squared norms.
    for (int k = tid; k < K; k += BLOCK) {
        const float* ek = se + k * D;
        float s = 0.f;
        #pragma unroll
        for (int d = 0; d < D; d++) s = fmaf(ek[d], ek[d], s);
        snorm[k] = s;
    }
    __syncthreads();

    const int base  = blockIdx.x * rows_per_cta;
    const int count = min(rows_per_cta, nrows - base);

    const int  row0 = base + tid;
    const int  row1 = base + tid + BLOCK;
    const bool v0   = (tid < count);
    const bool v1   = (tid + BLOCK < count);

    // x rows in registers as packed f32x2 (32 packs = 64 floats per row).
    unsigned long long xr0[32], xr1[32];
    float xn0 = 0.f, xn1 = 0.f;
    {
        const ulonglong2* p0 = (const ulonglong2*)(x + (size_t)row0 * D);
        const ulonglong2* p1 = (const ulonglong2*)(x + (size_t)row1 * D);
        #pragma unroll
        for (int j = 0; j < 16; j++) {
            ulonglong2 a = v0 ? p0[j] : make_ulonglong2(0ull, 0ull);
            ulonglong2 b = v1 ? p1[j] : make_ulonglong2(0ull, 0ull);
            xr0[2 * j] = a.x; xr0[2 * j + 1] = a.y;
            xr1[2 * j] = b.x; xr1[2 * j + 1] = b.y;
        }
        #pragma unroll
        for (int p = 0; p < 32; p++) {
            float2 a = unpack2(xr0[p]);
            float2 b = unpack2(xr1[p]);
            xn0 = fmaf(a.x, a.x, fmaf(a.y, a.y, xn0));
            xn1 = fmaf(b.x, b.x, fmaf(b.y, b.y, xn1));
        }
    }

    float best0 = FLT_MAX, best1 = FLT_MAX;
    int   bk0 = 0, bk1 = 0;

    for (int k = 0; k < K; k++) {
        const ulonglong2* ek = (const ulonglong2*)(se + k * D);
        unsigned long long a0 = 0, a1 = 0, a2 = 0, a3 = 0;   // row0 accums
        unsigned long long b0 = 0, b1 = 0, b2 = 0, b3 = 0;   // row1 accums
        #pragma unroll
        for (int j = 0; j < 16; j++) {
            ulonglong2 e = ek[j];    // broadcast LDS.128, shared by both rows
            if (j & 1) {
                a2 = ffma2(e.x, xr0[2 * j],     a2);
                a3 = ffma2(e.y, xr0[2 * j + 1], a3);
                b2 = ffma2(e.x, xr1[2 * j],     b2);
                b3 = ffma2(e.y, xr1[2 * j + 1], b3);
            } else {
                a0 = ffma2(e.x, xr0[2 * j],     a0);
                a1 = ffma2(e.y, xr0[2 * j + 1], a1);
                b0 = ffma2(e.x, xr1[2 * j],     b0);
                b1 = ffma2(e.y, xr1[2 * j + 1], b1);
            }
        }
        a0 = fadd2(fadd2(a0, a1), fadd2(a2, a3));
        b0 = fadd2(fadd2(b0, b1), fadd2(b2, b3));
        float2 sa = unpack2(a0);
        float2 sb = unpack2(b0);
        float dot0 = sa.x + sa.y;
        float dot1 = sb.x + sb.y;
        float nk = snorm[k];
        float d0 = fmaf(-2.f, dot0, nk);
        float d1 = fmaf(-2.f, dot1, nk);
        if (d0 < best0) { best0 = d0; bk0 = k; }
        if (d1 < best1) { best1 = d1; bk1 = k; }
    }

    double mysum = 0.0;
    if (v0) {
        mysum += (double)(xn0 + best0);
        float4* op = (float4*)(out + (size_t)row0 * D);
        const float4* eb = (const float4*)(se + bk0 * D);
        #pragma unroll
        for (int i = 0; i < 16; i++) op[i] = eb[i];
    }
    if (v1) {
        mysum += (double)(xn1 + best1);
        float4* op = (float4*)(out + (size_t)row1 * D);
        const float4* eb = (const float4*)(se + bk1 * D);
        #pragma unroll
        for (int i = 0; i < 16; i++) op[i] = eb[i];
    }

    // Block reduction (doubles), then one atomic per CTA.
    sred[tid] = mysum;
    __syncthreads();
    for (int s = 128; s > 0; s >>= 1) {
        if (tid < s && tid + s < BLOCK) sred[tid] += sred[tid + s];
        __syncthreads();
    }
    if (tid == 0) atomicAdd(&g_acc, sred[0]);
}

// loss = (1 + BETA) * sum_sq / (nrows * D), BETA = 0.25
__global__ void vq_finalize(float* __restrict__ out, int idx, double scale)
{
    out[idx] = (float)(g_acc * scale);
}

extern "C" void kernel_launch(void* const* d_in, const int* in_sizes, int n_in,
                              void* d_out, int out_size)
{
    const float* x   = (const float*)d_in[0];   // (64,32,32,64) = 4194304 floats
    const float* emb = (const float*)d_in[1];   // (64,512)      = 32768 floats
    float* out = (float*)d_out;

    const int nrows = in_sizes[0] / D;                    // 65536
    const int grid  = 148;                                // one wave on GB300
    const int rows_per_cta = (nrows + grid - 1) / grid;   // 443

    const int smem_bytes = (K * D + K) * (int)sizeof(float) + BLOCK * (int)sizeof(double);
    cudaFuncSetAttribute(vq_kernel, cudaFuncAttributeMaxDynamicSharedMemorySize, smem_bytes);

    vq_zero_acc<<<1, 1>>>();
    vq_kernel<<<grid, BLOCK, smem_bytes>>>(x, emb, out, nrows, rows_per_cta);

    if (out_size > nrows * D) {
        double scale = 1.25 / ((double)nrows * (double)D);
        vq_finalize<<<1, 1>>>(out, nrows * D, scale);
    }
}